// round 13
// baseline (speedup 1.0000x reference)
#include <cuda_runtime.h>
#include <cuda_bf16.h>
#include <cstdint>
#include <cstddef>

// Problem constants
#define BB   8
#define NN   1024
#define CC   768
#define HH   12
#define DH   64
#define CQKV 2304            // 3*C
#define MROWS (BB*NN)        // 8192

// Scratch: bf16 hi/lo pairs + permutation (device globals, allocation-free)
__device__ __nv_bfloat16 g_xh[(size_t)MROWS * CC],   g_xl[(size_t)MROWS * CC];
__device__ __nv_bfloat16 g_qkvh[(size_t)MROWS * CQKV], g_qkvl[(size_t)MROWS * CQKV];
__device__ __nv_bfloat16 g_atth[(size_t)MROWS * CC], g_attl[(size_t)MROWS * CC];
__device__ __nv_bfloat16 g_wqh[(size_t)CQKV * CC],   g_wql[(size_t)CQKV * CC];
__device__ __nv_bfloat16 g_wph[(size_t)CC * CC],     g_wpl[(size_t)CC * CC];
__device__ int g_perm[MROWS];    // [b][p] -> original token index (unmasked first)
__device__ int g_cnt[BB];        // unmasked count per batch

// ---------------------------------------------------------------------------
// Helpers
// ---------------------------------------------------------------------------
__device__ __forceinline__ uint32_t smem_u32(const void* p) {
    uint32_t a;
    asm("{ .reg .u64 t; cvta.to.shared.u64 t, %1; cvt.u32.u64 %0, t; }" : "=r"(a) : "l"(p));
    return a;
}
__device__ __forceinline__ void mma_bf16(float* d, const uint32_t* a, const uint32_t* b) {
    asm volatile(
        "mma.sync.aligned.m16n8k16.row.col.f32.bf16.bf16.f32 "
        "{%0,%1,%2,%3}, {%4,%5,%6,%7}, {%8,%9}, {%0,%1,%2,%3};"
        : "+f"(d[0]), "+f"(d[1]), "+f"(d[2]), "+f"(d[3])
        : "r"(a[0]), "r"(a[1]), "r"(a[2]), "r"(a[3]), "r"(b[0]), "r"(b[1]));
}
#define LDMX4(r0, r1, r2, r3, addr) \
    asm volatile("ldmatrix.sync.aligned.m8n8.x4.shared.b16 {%0,%1,%2,%3}, [%4];" \
        : "=r"(r0), "=r"(r1), "=r"(r2), "=r"(r3) : "r"(addr))
#define LDMX4T(r0, r1, r2, r3, addr) \
    asm volatile("ldmatrix.sync.aligned.m8n8.x4.trans.shared.b16 {%0,%1,%2,%3}, [%4];" \
        : "=r"(r0), "=r"(r1), "=r"(r2), "=r"(r3) : "r"(addr))
#define CP_ASYNC16(dst, src) \
    asm volatile("cp.async.cg.shared.global [%0], [%1], 16;" :: "r"(dst), "l"(src) : "memory")
#define CP_COMMIT()   asm volatile("cp.async.commit_group;" ::: "memory")
#define CP_WAIT(n)    asm volatile("cp.async.wait_group %0;" :: "n"(n) : "memory")

__device__ __forceinline__ void bsplit(float x, float& h, float& l) {
    h = __bfloat162float(__float2bfloat16(x));
    l = x - h;
}
__device__ __forceinline__ uint32_t packbf(float e0, float e1) {
    uint32_t d;
    asm("cvt.rn.bf16x2.f32 %0, %1, %2;" : "=r"(d) : "f"(e1), "f"(e0));
    return d;
}

// ---------------------------------------------------------------------------
// Compaction: per-batch stable permutation, unmasked (mask==0) first.
// ---------------------------------------------------------------------------
__global__ void compact_kernel(const int* __restrict__ mask,
                               int* __restrict__ perm, int* __restrict__ cnt)
{
    __shared__ int wc0[32], wo0[32], wc1[32], wo1[32];
    __shared__ int total_s;
    const int b = blockIdx.x, t = threadIdx.x;     // 1024 threads
    const int lane = t & 31, wid = t >> 5;
    const int m = mask[b * NN + t];
    unsigned bal = __ballot_sync(0xffffffffu, m == 0);
    int pre0 = __popc(bal  & ((1u << lane) - 1));
    int pre1 = __popc(~bal & ((1u << lane) - 1));
    if (lane == 0) { wc0[wid] = __popc(bal); wc1[wid] = __popc(~bal); }
    __syncthreads();
    if (t == 0) {
        int s0 = 0, s1 = 0;
        #pragma unroll
        for (int i = 0; i < 32; i++) {
            wo0[i] = s0; s0 += wc0[i];
            wo1[i] = s1; s1 += wc1[i];
        }
        cnt[b] = s0;
        total_s = s0;
    }
    __syncthreads();
    const int total = total_s;
    if (m == 0) perm[b * NN + wo0[wid] + pre0] = t;
    else        perm[b * NN + total + wo1[wid] + pre1] = t;
}

// ---------------------------------------------------------------------------
// Split with row gather (permuted order): dst[p] = split(src[perm[p]])
// ---------------------------------------------------------------------------
__global__ void splitg_kernel(const float* __restrict__ src,
                              __nv_bfloat16* __restrict__ dh,
                              __nv_bfloat16* __restrict__ dl,
                              const int* __restrict__ perm, int n4)
{
    int i = blockIdx.x * blockDim.x + threadIdx.x;
    if (i >= n4) return;
    int row = i / (CC / 4);                        // permuted global row
    int c4  = i - row * (CC / 4);
    int orig = (row & ~(NN - 1)) + perm[row];
    float4 v = *(const float4*)&src[(size_t)orig * CC + c4 * 4];
    float h0, l0, h1, l1, h2, l2, h3, l3;
    bsplit(v.x, h0, l0); bsplit(v.y, h1, l1);
    bsplit(v.z, h2, l2); bsplit(v.w, h3, l3);
    *(uint2*)&dh[i * 4] = make_uint2(packbf(h0, h1), packbf(h2, h3));
    *(uint2*)&dl[i * 4] = make_uint2(packbf(l0, l1), packbf(l2, l3));
}

// ---------------------------------------------------------------------------
// Fused transpose+split for BOTH weight matrices (blockIdx.z selects).
// ---------------------------------------------------------------------------
__global__ void tsplit2_kernel(const float* __restrict__ wq,
                               __nv_bfloat16* __restrict__ wqh, __nv_bfloat16* __restrict__ wql,
                               const float* __restrict__ wp,
                               __nv_bfloat16* __restrict__ wph, __nv_bfloat16* __restrict__ wpl)
{
    const int z = blockIdx.z;
    const int C = z ? CC : CQKV;
    if (z && blockIdx.x >= CC / 32) return;
    const float* src = z ? wp : wq;
    __nv_bfloat16* dh = z ? wph : wqh;
    __nv_bfloat16* dl = z ? wpl : wql;
    const int R = CC;

    __shared__ float tile[32][33];
    int cx = blockIdx.x * 32, ry = blockIdx.y * 32;
    #pragma unroll
    for (int i = 0; i < 32; i += 8)
        tile[threadIdx.y + i][threadIdx.x] = src[(size_t)(ry + threadIdx.y + i) * C + cx + threadIdx.x];
    __syncthreads();
    #pragma unroll
    for (int i = 0; i < 32; i += 8) {
        float v = tile[threadIdx.x][threadIdx.y + i];
        float h, l; bsplit(v, h, l);
        size_t o = (size_t)(cx + threadIdx.y + i) * R + ry + threadIdx.x;
        dh[o] = __float2bfloat16(h);
        dl[o] = __float2bfloat16(l);
    }
}

// ---------------------------------------------------------------------------
// bf16x3 GEMM templated on M-tile count: MT=4 -> BM=128 (QKV), MT=2 -> BM=64
// (proj; halves T_tile to fix last-kernel wave quantization).
// 3-stage single-sync pipeline, XOR-swizzled dense smem.
// mode 1 (QKV): skip K/V-column tiles for rows beyond cntPad.
// mode 0 (proj): fp32 out + bias, rows scattered back via perm.
// ---------------------------------------------------------------------------
template<int MT>
__global__ void __launch_bounds__(256, 2)
gemm_bf16(const __nv_bfloat16* __restrict__ Ah, const __nv_bfloat16* __restrict__ Al,
          const __nv_bfloat16* __restrict__ Bh, const __nv_bfloat16* __restrict__ Bl,
          const float* __restrict__ bias,
          float* __restrict__ Cf,
          __nv_bfloat16* __restrict__ Coh, __nv_bfloat16* __restrict__ Col,
          const int* __restrict__ cnt, const int* __restrict__ perm,
          int M, int N, int K, int mode)
{
    constexpr int BM    = MT * 32;            // 128 or 64
    constexpr int AMATG = BM * 64;            // bytes per A matrix per stage
    constexpr int BOFF  = 2 * AMATG;          // Bh offset
    constexpr int STGB  = 2 * AMATG + 16384;  // stage bytes

    const int m0 = blockIdx.y * BM;
    const int n0 = blockIdx.x * 128;

    // QKV: skip K/V tiles whose rows are all masked tokens
    if (mode == 1 && n0 >= CC) {
        int cp = (cnt[m0 >> 10] + 63) & ~63;
        if ((m0 & (NN - 1)) >= cp) return;
    }

    extern __shared__ __nv_bfloat16 smb[];
    const uint32_t smbase = smem_u32(smb);

    const int tid  = threadIdx.x;
    const int lane = tid & 31;
    const int wid  = tid >> 5;
    const int wm   = wid >> 2;
    const int wn   = wid & 3;
    const int nk   = K / 32;

    // ---- staging: thread owns row rb, chunk cch; A has BM rows, B has 128.
    const int rb  = tid >> 2;                // 0..63
    const int cch = tid & 3;
    const uint32_t dsoff = (uint32_t)rb * 64 + ((cch ^ ((rb >> 1) & 3)) << 4);
    const __nv_bfloat16* p0 = Ah + (size_t)(m0 + rb) * K + cch * 8;
    const __nv_bfloat16* p1 = Al + (size_t)(m0 + rb) * K + cch * 8;
    const __nv_bfloat16* p2 = Bh + (size_t)(n0 + rb) * K + cch * 8;
    const __nv_bfloat16* p3 = Bl + (size_t)(n0 + rb) * K + cch * 8;
    const size_t rstep = (size_t)64 * K;

    auto issue = [&](int st) {
        uint32_t sb = smbase + st * STGB + dsoff;
        CP_ASYNC16(sb,         p0);
        CP_ASYNC16(sb + AMATG, p1);
        if (MT == 4) {                       // second 64-row half of A
            CP_ASYNC16(sb + 4096,         p0 + rstep);
            CP_ASYNC16(sb + AMATG + 4096, p1 + rstep);
        }
        CP_ASYNC16(sb + BOFF,                p2);
        CP_ASYNC16(sb + BOFF + 4096,         p2 + rstep);
        CP_ASYNC16(sb + BOFF + 8192,         p3);
        CP_ASYNC16(sb + BOFF + 8192 + 4096,  p3 + rstep);
        CP_COMMIT();
        p0 += 32; p1 += 32; p2 += 32; p3 += 32;
    };

    // ---- fragment addressing (swizzled)
    uint32_t arow[MT]; int asw[MT];
    #pragma unroll
    for (int mi = 0; mi < MT; mi++) {
        int r = wm * (MT * 16) + mi * 16 + (lane & 15);
        arow[mi] = (uint32_t)r * 64;
        asw[mi]  = (r >> 1) & 3;
    }
    const int ac0 = lane >> 4;
    uint32_t brow[2]; int bsw[2];
    #pragma unroll
    for (int nt2 = 0; nt2 < 2; nt2++) {
        int r = wn * 32 + nt2 * 16 + (lane & 7) + ((lane & 16) ? 8 : 0);
        brow[nt2] = (uint32_t)r * 64;
        bsw[nt2]  = (r >> 1) & 3;
    }
    const int bc0 = (lane & 8) ? 1 : 0;

    float acc[MT][4][4] = {};

    issue(0);
    issue(1);
    int st = 0, stn = 2;
    for (int kc = 0; kc < nk; kc++) {
        if (kc == nk - 1) { CP_WAIT(0); } else { CP_WAIT(1); }
        __syncthreads();
        if (kc + 2 < nk) {
            issue(stn);
            if (++stn == 3) stn = 0;
        }

        const uint32_t base = smbase + st * STGB;
        #pragma unroll
        for (int s = 0; s < 2; s++) {
            uint32_t ah[MT][4], al[MT][4], bh[4][2], bl[4][2];
            #pragma unroll
            for (int mi = 0; mi < MT; mi++) {
                int c = s * 2 + ac0;
                uint32_t a = base + arow[mi] + (uint32_t)((c ^ asw[mi]) << 4);
                LDMX4(ah[mi][0], ah[mi][1], ah[mi][2], ah[mi][3], a);
                LDMX4(al[mi][0], al[mi][1], al[mi][2], al[mi][3], a + AMATG);
            }
            #pragma unroll
            for (int nt2 = 0; nt2 < 2; nt2++) {
                int c = s * 2 + bc0;
                uint32_t bx = base + BOFF + brow[nt2] + (uint32_t)((c ^ bsw[nt2]) << 4);
                LDMX4(bh[2*nt2][0], bh[2*nt2][1], bh[2*nt2+1][0], bh[2*nt2+1][1], bx);
                LDMX4(bl[2*nt2][0], bl[2*nt2][1], bl[2*nt2+1][0], bl[2*nt2+1][1], bx + 8192);
            }
            #pragma unroll
            for (int mi = 0; mi < MT; mi++)
                #pragma unroll
                for (int ni = 0; ni < 4; ni++)
                    mma_bf16(acc[mi][ni], ah[mi], bh[ni]);
            #pragma unroll
            for (int mi = 0; mi < MT; mi++)
                #pragma unroll
                for (int ni = 0; ni < 4; ni++)
                    mma_bf16(acc[mi][ni], ah[mi], bl[ni]);
            #pragma unroll
            for (int mi = 0; mi < MT; mi++)
                #pragma unroll
                for (int ni = 0; ni < 4; ni++)
                    mma_bf16(acc[mi][ni], al[mi], bh[ni]);
        }
        if (++st == 3) st = 0;
    }

    // Epilogue
    #pragma unroll
    for (int mi = 0; mi < MT; mi++) {
        const int row = m0 + wm * (MT * 16) + mi * 16 + (lane >> 2);
        #pragma unroll
        for (int ni = 0; ni < 4; ni++) {
            const int col = n0 + wn * 32 + ni * 8 + 2 * (lane & 3);
            float x0 = acc[mi][ni][0], x1 = acc[mi][ni][1];
            float y0 = acc[mi][ni][2], y1 = acc[mi][ni][3];
            if (mode == 0) {
                float b0 = bias ? bias[col] : 0.f, b1 = bias ? bias[col + 1] : 0.f;
                size_t or0 = (size_t)((row & ~(NN - 1)) + perm[row]);
                size_t or1 = (size_t)(((row + 8) & ~(NN - 1)) + perm[row + 8]);
                *(float2*)&Cf[or0 * N + col] = make_float2(x0 + b0, x1 + b1);
                *(float2*)&Cf[or1 * N + col] = make_float2(y0 + b0, y1 + b1);
            } else {
                float h0, l0, h1, l1;
                bsplit(x0, h0, l0); bsplit(x1, h1, l1);
                *(uint32_t*)&Coh[(size_t)row * N + col] = packbf(h0, h1);
                *(uint32_t*)&Col[(size_t)row * N + col] = packbf(l0, l1);
                bsplit(y0, h0, l0); bsplit(y1, h1, l1);
                *(uint32_t*)&Coh[(size_t)(row + 8) * N + col] = packbf(h0, h1);
                *(uint32_t*)&Col[(size_t)(row + 8) * N + col] = packbf(l0, l1);
            }
        }
    }
}

// ---------------------------------------------------------------------------
// Attention bf16x3 flash over COMPACTED keys (unchanged from round 12).
// ---------------------------------------------------------------------------
#define AMATB  8192                          // bytes: 64 rows x 128B
#define ASTGB  (4 * AMATB)                   // Kh|Kl|Vh|Vl = 32768 B

__global__ void __launch_bounds__(256, 2)
attn_mma(const __nv_bfloat16* __restrict__ qh_g, const __nv_bfloat16* __restrict__ ql_g,
         const int* __restrict__ cntp,
         __nv_bfloat16* __restrict__ oh_g, __nv_bfloat16* __restrict__ ol_g)
{
    extern __shared__ __nv_bfloat16 sma[];
    const uint32_t smbase = smem_u32(sma);

    const int t    = threadIdx.x;
    const int lane = t & 31;
    const int w    = t >> 5;
    const int q0   = blockIdx.x * 128;
    const int h    = blockIdx.y;
    const int b    = blockIdx.z;
    const size_t rowb = (size_t)b * NN;
    const int r0 = q0 + w * 16;
    const int qr = lane >> 2;
    const int qc = (lane & 3) * 2;

    const int cnt = cntp[b];
    int NT = (cnt + 63) >> 6;
    if (NT < 1) NT = 1;

    // ---- K/V staging state
    const int rb  = t >> 3;                  // 0..31
    const int cch = t & 7;
    const uint32_t dsoff = (uint32_t)rb * 128 + ((cch ^ (rb & 7)) << 4);
    const __nv_bfloat16* pH = qh_g + (rowb + rb) * CQKV + CC + h * DH + cch * 8;
    const __nv_bfloat16* pL = ql_g + (rowb + rb) * CQKV + CC + h * DH + cch * 8;
    const size_t rstep = (size_t)32 * CQKV;
    auto issue = [&](int st) {
        uint32_t sb = smbase + st * ASTGB + dsoff;
        CP_ASYNC16(sb,                 pH);      CP_ASYNC16(sb + 4096,             pH + rstep);
        CP_ASYNC16(sb + AMATB,         pL);      CP_ASYNC16(sb + AMATB + 4096,     pL + rstep);
        CP_ASYNC16(sb + 2 * AMATB,     pH + CC); CP_ASYNC16(sb + 2 * AMATB + 4096, pH + CC + rstep);
        CP_ASYNC16(sb + 3 * AMATB,     pL + CC); CP_ASYNC16(sb + 3 * AMATB + 4096, pL + CC + rstep);
        CP_COMMIT();
        pH += (size_t)64 * CQKV;
        pL += (size_t)64 * CQKV;
    };

    // ---- Overlapped prologue: Q tile -> stage-2 smem; KV stage 0/1 in flight
    {
        const __nv_bfloat16* qsH = qh_g + (rowb + q0) * CQKV + h * DH;
        const __nv_bfloat16* qsL = ql_g + (rowb + q0) * CQKV + h * DH;
        const uint32_t qbase = smbase + 2 * ASTGB;
        #pragma unroll
        for (int i = 0; i < 4; i++) {
            int idx = t + i * 256;
            int row = idx >> 3, c = idx & 7;
            uint32_t d = qbase + (uint32_t)row * 128 + (uint32_t)((c ^ (row & 7)) << 4);
            CP_ASYNC16(d,         qsH + (size_t)row * CQKV + c * 8);
            CP_ASYNC16(d + 16384, qsL + (size_t)row * CQKV + c * 8);
        }
        CP_COMMIT();           // group Q
        issue(0);              // group KV0
        issue(1);              // group KV1
    }

    uint32_t qh[4][4], ql[4][4];
    {
        CP_WAIT(2);
        __syncthreads();
        const uint32_t qbase = smbase + 2 * ASTGB;
        #pragma unroll
        for (int ks = 0; ks < 4; ks++) {
            int rr = w * 16 + (lane & 15);
            int c  = ks * 2 + (lane >> 4);
            uint32_t a = qbase + (uint32_t)rr * 128 + (uint32_t)((c ^ (rr & 7)) << 4);
            LDMX4(qh[ks][0], qh[ks][1], qh[ks][2], qh[ks][3], a);
            LDMX4(ql[ks][0], ql[ks][1], ql[ks][2], ql[ks][3], a + 16384);
        }
    }

    // ---- fragment addressing
    const int fsw = lane & 7;
    uint32_t krow[2];
    #pragma unroll
    for (int jj = 0; jj < 2; jj++)
        krow[jj] = (uint32_t)(jj * 16 + (lane & 7) + ((lane & 16) ? 8 : 0)) * 128;
    const int kc0 = (lane & 8) ? 1 : 0;
    const uint32_t vrow = (uint32_t)((lane & 7) + ((lane & 8) ? 8 : 0)) * 128;
    const int vc0 = (lane & 16) ? 1 : 0;

    float oacc[8][4] = {};
    float lsum0 = 0.f, lsum1 = 0.f;

    int st = 0, stn = 2;
    for (int jt = 0; jt < NT; jt++) {
        if (jt == NT - 1) { CP_WAIT(0); } else { CP_WAIT(1); }
        __syncthreads();
        if (jt + 2 < NT) {
            issue(stn);
            if (++stn == 3) stn = 0;
        }

        const uint32_t base = smbase + st * ASTGB;

        #pragma unroll
        for (int half = 0; half < 2; half++) {
            float sacc[4][4] = {};
            #pragma unroll
            for (int ks = 0; ks < 4; ks++) {
                uint32_t bh[4][2], bl[4][2];
                #pragma unroll
                for (int jj = 0; jj < 2; jj++) {
                    int c = ks * 2 + kc0;
                    uint32_t a = base + krow[jj] + (uint32_t)(half * 32 * 128)
                               + (uint32_t)((c ^ fsw) << 4);
                    LDMX4(bh[2*jj][0], bh[2*jj][1], bh[2*jj+1][0], bh[2*jj+1][1], a);
                    LDMX4(bl[2*jj][0], bl[2*jj][1], bl[2*jj+1][0], bl[2*jj+1][1], a + AMATB);
                }
                #pragma unroll
                for (int n = 0; n < 4; n++) mma_bf16(sacc[n], qh[ks], bh[n]);
                #pragma unroll
                for (int n = 0; n < 4; n++) mma_bf16(sacc[n], qh[ks], bl[n]);
                #pragma unroll
                for (int n = 0; n < 4; n++) mma_bf16(sacc[n], ql[ks], bh[n]);
            }

            uint32_t pah[2][4], pal[2][4];
            #pragma unroll
            for (int n = 0; n < 4; n++) {
                int c0 = jt * 64 + half * 32 + n * 8 + qc;
                bool mk0 = c0 >= cnt, mk1 = (c0 + 1) >= cnt;
                float p00 = mk0 ? 0.f : __expf(sacc[n][0] * 0.125f);
                float p01 = mk1 ? 0.f : __expf(sacc[n][1] * 0.125f);
                float p10 = mk0 ? 0.f : __expf(sacc[n][2] * 0.125f);
                float p11 = mk1 ? 0.f : __expf(sacc[n][3] * 0.125f);
                lsum0 += p00 + p01;
                lsum1 += p10 + p11;
                float h00, l00, h01, l01, h10, l10, h11, l11;
                bsplit(p00, h00, l00); bsplit(p01, h01, l01);
                bsplit(p10, h10, l10); bsplit(p11, h11, l11);
                const int j = n >> 1, o2 = (n & 1) * 2;
                pah[j][o2 + 0] = packbf(h00, h01);
                pah[j][o2 + 1] = packbf(h10, h11);
                pal[j][o2 + 0] = packbf(l00, l01);
                pal[j][o2 + 1] = packbf(l10, l11);
            }

            #pragma unroll
            for (int j = 0; j < 2; j++) {
                #pragma unroll
                for (int g = 0; g < 2; g++) {
                    uint32_t vha[4], vla[4], vhb[4], vlb[4];
                    {
                        int ca = (2 * g) * 2 + vc0;
                        uint32_t aa = base + 2 * AMATB + vrow
                                    + (uint32_t)((half * 32 + j * 16) * 128)
                                    + (uint32_t)((ca ^ fsw) << 4);
                        LDMX4T(vha[0], vha[1], vha[2], vha[3], aa);
                        LDMX4T(vla[0], vla[1], vla[2], vla[3], aa + AMATB);
                        int cb = (2 * g + 1) * 2 + vc0;
                        uint32_t ab = base + 2 * AMATB + vrow
                                    + (uint32_t)((half * 32 + j * 16) * 128)
                                    + (uint32_t)((cb ^ fsw) << 4);
                        LDMX4T(vhb[0], vhb[1], vhb[2], vhb[3], ab);
                        LDMX4T(vlb[0], vlb[1], vlb[2], vlb[3], ab + AMATB);
                    }
                    float* o0 = oacc[4 * g + 0];
                    float* o1 = oacc[4 * g + 1];
                    float* o2 = oacc[4 * g + 2];
                    float* o3 = oacc[4 * g + 3];
                    mma_bf16(o0, pah[j], &vha[0]);
                    mma_bf16(o1, pah[j], &vha[2]);
                    mma_bf16(o2, pah[j], &vhb[0]);
                    mma_bf16(o3, pah[j], &vhb[2]);
                    mma_bf16(o0, pah[j], &vla[0]);
                    mma_bf16(o1, pah[j], &vla[2]);
                    mma_bf16(o2, pah[j], &vlb[0]);
                    mma_bf16(o3, pah[j], &vlb[2]);
                    mma_bf16(o0, pal[j], &vha[0]);
                    mma_bf16(o1, pal[j], &vha[2]);
                    mma_bf16(o2, pal[j], &vhb[0]);
                    mma_bf16(o3, pal[j], &vhb[2]);
                }
            }
        }
        if (++st == 3) st = 0;
    }

    // ---- Normalize, split, store bf16 hi/lo (rows stay permuted)
    lsum0 += __shfl_xor_sync(0xffffffffu, lsum0, 1);
    lsum0 += __shfl_xor_sync(0xffffffffu, lsum0, 2);
    lsum1 += __shfl_xor_sync(0xffffffffu, lsum1, 1);
    lsum1 += __shfl_xor_sync(0xffffffffu, lsum1, 2);
    const float inv0 = 1.0f / lsum0;
    const float inv1 = 1.0f / lsum1;

    #pragma unroll
    for (int d = 0; d < 8; d++) {
        int col = h * DH + d * 8 + qc;
        size_t row = rowb + r0 + qr;
        float h0, l0, h1, l1;
        bsplit(oacc[d][0] * inv0, h0, l0); bsplit(oacc[d][1] * inv0, h1, l1);
        *(uint32_t*)&oh_g[row * CC + col] = packbf(h0, h1);
        *(uint32_t*)&ol_g[row * CC + col] = packbf(l0, l1);
        bsplit(oacc[d][2] * inv1, h0, l0); bsplit(oacc[d][3] * inv1, h1, l1);
        *(uint32_t*)&oh_g[(row + 8) * CC + col] = packbf(h0, h1);
        *(uint32_t*)&ol_g[(row + 8) * CC + col] = packbf(l0, l1);
    }
}

// ---------------------------------------------------------------------------
extern "C" void kernel_launch(void* const* d_in, const int* in_sizes, int n_in,
                              void* d_out, int out_size)
{
    const float* x      = (const float*)d_in[0];
    const int*   mask   = (const int*)  d_in[1];
    const float* w_qkv  = (const float*)d_in[2];
    const float* w_proj = (const float*)d_in[3];
    const float* b_proj = (const float*)d_in[4];
    float* out = (float*)d_out;

    void *pxh, *pxl, *pqh, *pql, *pah, *pal, *pwqh, *pwql, *pwph, *pwpl, *pperm, *pcnt;
    cudaGetSymbolAddress(&pxh, g_xh);   cudaGetSymbolAddress(&pxl, g_xl);
    cudaGetSymbolAddress(&pqh, g_qkvh); cudaGetSymbolAddress(&pql, g_qkvl);
    cudaGetSymbolAddress(&pah, g_atth); cudaGetSymbolAddress(&pal, g_attl);
    cudaGetSymbolAddress(&pwqh, g_wqh); cudaGetSymbolAddress(&pwql, g_wql);
    cudaGetSymbolAddress(&pwph, g_wph); cudaGetSymbolAddress(&pwpl, g_wpl);
    cudaGetSymbolAddress(&pperm, g_perm); cudaGetSymbolAddress(&pcnt, g_cnt);
    __nv_bfloat16 *xh = (__nv_bfloat16*)pxh,  *xl = (__nv_bfloat16*)pxl;
    __nv_bfloat16 *qh = (__nv_bfloat16*)pqh,  *ql = (__nv_bfloat16*)pql;
    __nv_bfloat16 *ah = (__nv_bfloat16*)pah,  *al = (__nv_bfloat16*)pal;
    __nv_bfloat16 *wqh = (__nv_bfloat16*)pwqh, *wql = (__nv_bfloat16*)pwql;
    __nv_bfloat16 *wph = (__nv_bfloat16*)pwph, *wpl = (__nv_bfloat16*)pwpl;
    int *perm = (int*)pperm, *cnt = (int*)pcnt;

    const int GEMM_SMEM4 = 3 * 32768;         // MT=4: 98304 B
    const int GEMM_SMEM2 = 3 * 24576;         // MT=2: 73728 B
    const int ATTN_SMEM  = 3 * ASTGB;         // 98304 B
    cudaFuncSetAttribute(gemm_bf16<4>, cudaFuncAttributeMaxDynamicSharedMemorySize, GEMM_SMEM4);
    cudaFuncSetAttribute(gemm_bf16<2>, cudaFuncAttributeMaxDynamicSharedMemorySize, GEMM_SMEM2);
    cudaFuncSetAttribute(attn_mma, cudaFuncAttributeMaxDynamicSharedMemorySize, ATTN_SMEM);

    // 0) Per-batch compaction permutation (unmasked keys first)
    compact_kernel<<<BB, NN>>>(mask, perm, cnt);
    // 1) Split X in permuted row order; fused transpose+split of both weights
    splitg_kernel<<<(MROWS * CC / 4 + 255) / 256, 256>>>(x, xh, xl, perm, MROWS * CC / 4);
    {
        dim3 blk(32, 8);
        tsplit2_kernel<<<dim3(CQKV / 32, CC / 32, 2), blk>>>(w_qkv, wqh, wql,
                                                             w_proj, wph, wpl);
    }
    // 2) QKV GEMM (BM=128) -> bf16 hi/lo (K/V tiles for masked rows skipped)
    {
        dim3 grid(CQKV / 128, MROWS / 128);
        gemm_bf16<4><<<grid, 256, GEMM_SMEM4>>>(xh, xl, wqh, wql, nullptr,
                                                nullptr, qh, ql, cnt, perm,
                                                MROWS, CQKV, CC, 1);
    }
    // 3) Attention over compacted keys -> bf16 hi/lo
    {
        dim3 grid(NN / 128, HH, BB);
        attn_mma<<<grid, 256, ATTN_SMEM>>>(qh, ql, cnt, ah, al);
    }
    // 4) Output projection (BM=64 to kill the last-wave tail) + bias -> fp32
    {
        dim3 grid(CC / 128, MROWS / 64);
        gemm_bf16<2><<<grid, 256, GEMM_SMEM2>>>(ah, al, wph, wpl, b_proj,
                                                out, nullptr, nullptr, cnt, perm,
                                                MROWS, CC, CC, 0);
    }
}

// round 14
// speedup vs baseline: 1.0687x; 1.0687x over previous
#include <cuda_runtime.h>
#include <cuda_bf16.h>
#include <cstdint>
#include <cstddef>

// Problem constants
#define BB   8
#define NN   1024
#define CC   768
#define HH   12
#define DH   64
#define CQKV 2304            // 3*C
#define MROWS (BB*NN)        // 8192

// Scratch: bf16 hi/lo pairs + permutation (device globals, allocation-free)
__device__ __nv_bfloat16 g_xh[(size_t)MROWS * CC],   g_xl[(size_t)MROWS * CC];
__device__ __nv_bfloat16 g_qkvh[(size_t)MROWS * CQKV], g_qkvl[(size_t)MROWS * CQKV];
__device__ __nv_bfloat16 g_atth[(size_t)MROWS * CC], g_attl[(size_t)MROWS * CC];
__device__ __nv_bfloat16 g_wqh[(size_t)CQKV * CC],   g_wql[(size_t)CQKV * CC];
__device__ __nv_bfloat16 g_wph[(size_t)CC * CC],     g_wpl[(size_t)CC * CC];
__device__ int g_perm[MROWS];    // [b][p] -> original token index (unmasked first)
__device__ int g_cnt[BB];        // unmasked count per batch

// ---------------------------------------------------------------------------
// Helpers
// ---------------------------------------------------------------------------
__device__ __forceinline__ uint32_t smem_u32(const void* p) {
    uint32_t a;
    asm("{ .reg .u64 t; cvta.to.shared.u64 t, %1; cvt.u32.u64 %0, t; }" : "=r"(a) : "l"(p));
    return a;
}
__device__ __forceinline__ void mma_bf16(float* d, const uint32_t* a, const uint32_t* b) {
    asm volatile(
        "mma.sync.aligned.m16n8k16.row.col.f32.bf16.bf16.f32 "
        "{%0,%1,%2,%3}, {%4,%5,%6,%7}, {%8,%9}, {%0,%1,%2,%3};"
        : "+f"(d[0]), "+f"(d[1]), "+f"(d[2]), "+f"(d[3])
        : "r"(a[0]), "r"(a[1]), "r"(a[2]), "r"(a[3]), "r"(b[0]), "r"(b[1]));
}
#define LDMX4(r0, r1, r2, r3, addr) \
    asm volatile("ldmatrix.sync.aligned.m8n8.x4.shared.b16 {%0,%1,%2,%3}, [%4];" \
        : "=r"(r0), "=r"(r1), "=r"(r2), "=r"(r3) : "r"(addr))
#define LDMX4T(r0, r1, r2, r3, addr) \
    asm volatile("ldmatrix.sync.aligned.m8n8.x4.trans.shared.b16 {%0,%1,%2,%3}, [%4];" \
        : "=r"(r0), "=r"(r1), "=r"(r2), "=r"(r3) : "r"(addr))
#define CP_ASYNC16(dst, src) \
    asm volatile("cp.async.cg.shared.global [%0], [%1], 16;" :: "r"(dst), "l"(src) : "memory")
#define CP_COMMIT()   asm volatile("cp.async.commit_group;" ::: "memory")
#define CP_WAIT(n)    asm volatile("cp.async.wait_group %0;" :: "n"(n) : "memory")

__device__ __forceinline__ void bsplit(float x, float& h, float& l) {
    h = __bfloat162float(__float2bfloat16(x));
    l = x - h;
}
__device__ __forceinline__ uint32_t packbf(float e0, float e1) {
    uint32_t d;
    asm("cvt.rn.bf16x2.f32 %0, %1, %2;" : "=r"(d) : "f"(e1), "f"(e0));
    return d;
}

// ---------------------------------------------------------------------------
// Compaction: per-batch stable permutation, unmasked (mask==0) first.
// ---------------------------------------------------------------------------
__global__ void compact_kernel(const int* __restrict__ mask,
                               int* __restrict__ perm, int* __restrict__ cnt)
{
    __shared__ int wc0[32], wo0[32], wc1[32], wo1[32];
    __shared__ int total_s;
    const int b = blockIdx.x, t = threadIdx.x;     // 1024 threads
    const int lane = t & 31, wid = t >> 5;
    const int m = mask[b * NN + t];
    unsigned bal = __ballot_sync(0xffffffffu, m == 0);
    int pre0 = __popc(bal  & ((1u << lane) - 1));
    int pre1 = __popc(~bal & ((1u << lane) - 1));
    if (lane == 0) { wc0[wid] = __popc(bal); wc1[wid] = __popc(~bal); }
    __syncthreads();
    if (t == 0) {
        int s0 = 0, s1 = 0;
        #pragma unroll
        for (int i = 0; i < 32; i++) {
            wo0[i] = s0; s0 += wc0[i];
            wo1[i] = s1; s1 += wc1[i];
        }
        cnt[b] = s0;
        total_s = s0;
    }
    __syncthreads();
    const int total = total_s;
    if (m == 0) perm[b * NN + wo0[wid] + pre0] = t;
    else        perm[b * NN + total + wo1[wid] + pre1] = t;
}

// ---------------------------------------------------------------------------
// Split with row gather (permuted order): dst[p] = split(src[perm[p]])
// ---------------------------------------------------------------------------
__global__ void splitg_kernel(const float* __restrict__ src,
                              __nv_bfloat16* __restrict__ dh,
                              __nv_bfloat16* __restrict__ dl,
                              const int* __restrict__ perm, int n4)
{
    int i = blockIdx.x * blockDim.x + threadIdx.x;
    if (i >= n4) return;
    int row = i / (CC / 4);                        // permuted global row
    int c4  = i - row * (CC / 4);
    int orig = (row & ~(NN - 1)) + perm[row];
    float4 v = *(const float4*)&src[(size_t)orig * CC + c4 * 4];
    float h0, l0, h1, l1, h2, l2, h3, l3;
    bsplit(v.x, h0, l0); bsplit(v.y, h1, l1);
    bsplit(v.z, h2, l2); bsplit(v.w, h3, l3);
    *(uint2*)&dh[i * 4] = make_uint2(packbf(h0, h1), packbf(h2, h3));
    *(uint2*)&dl[i * 4] = make_uint2(packbf(l0, l1), packbf(l2, l3));
}

// ---------------------------------------------------------------------------
// Fused transpose+split for BOTH weight matrices (blockIdx.z selects).
// ---------------------------------------------------------------------------
__global__ void tsplit2_kernel(const float* __restrict__ wq,
                               __nv_bfloat16* __restrict__ wqh, __nv_bfloat16* __restrict__ wql,
                               const float* __restrict__ wp,
                               __nv_bfloat16* __restrict__ wph, __nv_bfloat16* __restrict__ wpl)
{
    const int z = blockIdx.z;
    const int C = z ? CC : CQKV;
    if (z && blockIdx.x >= CC / 32) return;
    const float* src = z ? wp : wq;
    __nv_bfloat16* dh = z ? wph : wqh;
    __nv_bfloat16* dl = z ? wpl : wql;
    const int R = CC;

    __shared__ float tile[32][33];
    int cx = blockIdx.x * 32, ry = blockIdx.y * 32;
    #pragma unroll
    for (int i = 0; i < 32; i += 8)
        tile[threadIdx.y + i][threadIdx.x] = src[(size_t)(ry + threadIdx.y + i) * C + cx + threadIdx.x];
    __syncthreads();
    #pragma unroll
    for (int i = 0; i < 32; i += 8) {
        float v = tile[threadIdx.x][threadIdx.y + i];
        float h, l; bsplit(v, h, l);
        size_t o = (size_t)(cx + threadIdx.y + i) * R + ry + threadIdx.x;
        dh[o] = __float2bfloat16(h);
        dl[o] = __float2bfloat16(l);
    }
}

// ---------------------------------------------------------------------------
// bf16x3 GEMM (BM=128), per-batch row range via mbase. 3-stage pipeline,
// XOR-swizzled dense smem. mode 1 (QKV): skip K/V tiles beyond cntPad.
// mode 0 (proj): fp32 out + bias, rows scattered back via perm.
// ---------------------------------------------------------------------------
#define GMATB  8192                          // bytes: 128 rows x 64B
#define GSTGB  (4 * GMATB)                   // Ah|Al|Bh|Bl = 32768 B

__global__ void __launch_bounds__(256, 2)
gemm_bf16(const __nv_bfloat16* __restrict__ Ah, const __nv_bfloat16* __restrict__ Al,
          const __nv_bfloat16* __restrict__ Bh, const __nv_bfloat16* __restrict__ Bl,
          const float* __restrict__ bias,
          float* __restrict__ Cf,
          __nv_bfloat16* __restrict__ Coh, __nv_bfloat16* __restrict__ Col,
          const int* __restrict__ cnt, const int* __restrict__ perm,
          int mbase, int N, int K, int mode)
{
    const int m0 = mbase + blockIdx.y * 128;
    const int n0 = blockIdx.x * 128;

    // QKV: skip K/V tiles whose rows are all masked tokens
    if (mode == 1 && n0 >= CC) {
        int cp = (cnt[m0 >> 10] + 63) & ~63;
        if ((m0 & (NN - 1)) >= cp) return;
    }

    extern __shared__ __nv_bfloat16 smb[];
    const uint32_t smbase = smem_u32(smb);

    const int tid  = threadIdx.x;
    const int lane = tid & 31;
    const int wid  = tid >> 5;
    const int wm   = wid >> 2;
    const int wn   = wid & 3;
    const int nk   = K / 32;

    // ---- staging: thread owns (rowbase, rowbase+64) x chunk cch in all 4 mats
    const int rb  = tid >> 2;                // 0..63
    const int cch = tid & 3;
    const uint32_t dsoff = (uint32_t)rb * 64 + ((cch ^ ((rb >> 1) & 3)) << 4);
    const __nv_bfloat16* p0 = Ah + (size_t)(m0 + rb) * K + cch * 8;
    const __nv_bfloat16* p1 = Al + (size_t)(m0 + rb) * K + cch * 8;
    const __nv_bfloat16* p2 = Bh + (size_t)(n0 + rb) * K + cch * 8;
    const __nv_bfloat16* p3 = Bl + (size_t)(n0 + rb) * K + cch * 8;
    const size_t rstep = (size_t)64 * K;

    auto issue = [&](int st) {
        uint32_t sb = smbase + st * GSTGB + dsoff;
        CP_ASYNC16(sb,                 p0); CP_ASYNC16(sb + 4096,             p0 + rstep);
        CP_ASYNC16(sb + GMATB,         p1); CP_ASYNC16(sb + GMATB + 4096,     p1 + rstep);
        CP_ASYNC16(sb + 2 * GMATB,     p2); CP_ASYNC16(sb + 2 * GMATB + 4096, p2 + rstep);
        CP_ASYNC16(sb + 3 * GMATB,     p3); CP_ASYNC16(sb + 3 * GMATB + 4096, p3 + rstep);
        CP_COMMIT();
        p0 += 32; p1 += 32; p2 += 32; p3 += 32;
    };

    // ---- fragment addressing (swizzled)
    uint32_t arow[4]; int asw[4];
    #pragma unroll
    for (int mi = 0; mi < 4; mi++) {
        int r = wm * 64 + mi * 16 + (lane & 15);
        arow[mi] = (uint32_t)r * 64;
        asw[mi]  = (r >> 1) & 3;
    }
    const int ac0 = lane >> 4;
    uint32_t brow[2]; int bsw[2];
    #pragma unroll
    for (int nt2 = 0; nt2 < 2; nt2++) {
        int r = wn * 32 + nt2 * 16 + (lane & 7) + ((lane & 16) ? 8 : 0);
        brow[nt2] = (uint32_t)r * 64;
        bsw[nt2]  = (r >> 1) & 3;
    }
    const int bc0 = (lane & 8) ? 1 : 0;

    float acc[4][4][4] = {};

    issue(0);
    issue(1);
    int st = 0, stn = 2;
    for (int kc = 0; kc < nk; kc++) {
        if (kc == nk - 1) { CP_WAIT(0); } else { CP_WAIT(1); }
        __syncthreads();
        if (kc + 2 < nk) {
            issue(stn);
            if (++stn == 3) stn = 0;
        }

        const uint32_t base = smbase + st * GSTGB;
        #pragma unroll
        for (int s = 0; s < 2; s++) {
            uint32_t ah[4][4], al[4][4], bh[4][2], bl[4][2];
            #pragma unroll
            for (int mi = 0; mi < 4; mi++) {
                int c = s * 2 + ac0;
                uint32_t a = base + arow[mi] + (uint32_t)((c ^ asw[mi]) << 4);
                LDMX4(ah[mi][0], ah[mi][1], ah[mi][2], ah[mi][3], a);
                LDMX4(al[mi][0], al[mi][1], al[mi][2], al[mi][3], a + GMATB);
            }
            #pragma unroll
            for (int nt2 = 0; nt2 < 2; nt2++) {
                int c = s * 2 + bc0;
                uint32_t bx = base + 2 * GMATB + brow[nt2] + (uint32_t)((c ^ bsw[nt2]) << 4);
                LDMX4(bh[2*nt2][0], bh[2*nt2][1], bh[2*nt2+1][0], bh[2*nt2+1][1], bx);
                LDMX4(bl[2*nt2][0], bl[2*nt2][1], bl[2*nt2+1][0], bl[2*nt2+1][1], bx + GMATB);
            }
            #pragma unroll
            for (int mi = 0; mi < 4; mi++)
                #pragma unroll
                for (int ni = 0; ni < 4; ni++)
                    mma_bf16(acc[mi][ni], ah[mi], bh[ni]);
            #pragma unroll
            for (int mi = 0; mi < 4; mi++)
                #pragma unroll
                for (int ni = 0; ni < 4; ni++)
                    mma_bf16(acc[mi][ni], ah[mi], bl[ni]);
            #pragma unroll
            for (int mi = 0; mi < 4; mi++)
                #pragma unroll
                for (int ni = 0; ni < 4; ni++)
                    mma_bf16(acc[mi][ni], al[mi], bh[ni]);
        }
        if (++st == 3) st = 0;
    }

    // Epilogue
    #pragma unroll
    for (int mi = 0; mi < 4; mi++) {
        const int row = m0 + wm * 64 + mi * 16 + (lane >> 2);
        #pragma unroll
        for (int ni = 0; ni < 4; ni++) {
            const int col = n0 + wn * 32 + ni * 8 + 2 * (lane & 3);
            float x0 = acc[mi][ni][0], x1 = acc[mi][ni][1];
            float y0 = acc[mi][ni][2], y1 = acc[mi][ni][3];
            if (mode == 0) {
                float b0 = bias ? bias[col] : 0.f, b1 = bias ? bias[col + 1] : 0.f;
                size_t or0 = (size_t)((row & ~(NN - 1)) + perm[row]);
                size_t or1 = (size_t)(((row + 8) & ~(NN - 1)) + perm[row + 8]);
                *(float2*)&Cf[or0 * N + col] = make_float2(x0 + b0, x1 + b1);
                *(float2*)&Cf[or1 * N + col] = make_float2(y0 + b0, y1 + b1);
            } else {
                float h0, l0, h1, l1;
                bsplit(x0, h0, l0); bsplit(x1, h1, l1);
                *(uint32_t*)&Coh[(size_t)row * N + col] = packbf(h0, h1);
                *(uint32_t*)&Col[(size_t)row * N + col] = packbf(l0, l1);
                bsplit(y0, h0, l0); bsplit(y1, h1, l1);
                *(uint32_t*)&Coh[(size_t)(row + 8) * N + col] = packbf(h0, h1);
                *(uint32_t*)&Col[(size_t)(row + 8) * N + col] = packbf(l0, l1);
            }
        }
    }
}

// ---------------------------------------------------------------------------
// Attention bf16x3 flash over COMPACTED keys, per-batch (bsel).
// Q staged into stage-2 smem concurrently with KV stages 0/1.
// ---------------------------------------------------------------------------
#define AMATB  8192                          // bytes: 64 rows x 128B
#define ASTGB  (4 * AMATB)                   // Kh|Kl|Vh|Vl = 32768 B

__global__ void __launch_bounds__(256, 2)
attn_mma(const __nv_bfloat16* __restrict__ qh_g, const __nv_bfloat16* __restrict__ ql_g,
         const int* __restrict__ cntp,
         __nv_bfloat16* __restrict__ oh_g, __nv_bfloat16* __restrict__ ol_g,
         int bsel)
{
    extern __shared__ __nv_bfloat16 sma[];
    const uint32_t smbase = smem_u32(sma);

    const int t    = threadIdx.x;
    const int lane = t & 31;
    const int w    = t >> 5;
    const int q0   = blockIdx.x * 128;
    const int h    = blockIdx.y;
    const int b    = bsel;
    const size_t rowb = (size_t)b * NN;
    const int r0 = q0 + w * 16;
    const int qr = lane >> 2;
    const int qc = (lane & 3) * 2;

    const int cnt = cntp[b];
    int NT = (cnt + 63) >> 6;
    if (NT < 1) NT = 1;

    // ---- K/V staging state
    const int rb  = t >> 3;                  // 0..31
    const int cch = t & 7;
    const uint32_t dsoff = (uint32_t)rb * 128 + ((cch ^ (rb & 7)) << 4);
    const __nv_bfloat16* pH = qh_g + (rowb + rb) * CQKV + CC + h * DH + cch * 8;
    const __nv_bfloat16* pL = ql_g + (rowb + rb) * CQKV + CC + h * DH + cch * 8;
    const size_t rstep = (size_t)32 * CQKV;
    auto issue = [&](int st) {
        uint32_t sb = smbase + st * ASTGB + dsoff;
        CP_ASYNC16(sb,                 pH);      CP_ASYNC16(sb + 4096,             pH + rstep);
        CP_ASYNC16(sb + AMATB,         pL);      CP_ASYNC16(sb + AMATB + 4096,     pL + rstep);
        CP_ASYNC16(sb + 2 * AMATB,     pH + CC); CP_ASYNC16(sb + 2 * AMATB + 4096, pH + CC + rstep);
        CP_ASYNC16(sb + 3 * AMATB,     pL + CC); CP_ASYNC16(sb + 3 * AMATB + 4096, pL + CC + rstep);
        CP_COMMIT();
        pH += (size_t)64 * CQKV;
        pL += (size_t)64 * CQKV;
    };

    // ---- Overlapped prologue: Q tile -> stage-2 smem; KV stage 0/1 in flight
    {
        const __nv_bfloat16* qsH = qh_g + (rowb + q0) * CQKV + h * DH;
        const __nv_bfloat16* qsL = ql_g + (rowb + q0) * CQKV + h * DH;
        const uint32_t qbase = smbase + 2 * ASTGB;
        #pragma unroll
        for (int i = 0; i < 4; i++) {
            int idx = t + i * 256;
            int row = idx >> 3, c = idx & 7;
            uint32_t d = qbase + (uint32_t)row * 128 + (uint32_t)((c ^ (row & 7)) << 4);
            CP_ASYNC16(d,         qsH + (size_t)row * CQKV + c * 8);
            CP_ASYNC16(d + 16384, qsL + (size_t)row * CQKV + c * 8);
        }
        CP_COMMIT();           // group Q
        issue(0);              // group KV0
        issue(1);              // group KV1
    }

    uint32_t qh[4][4], ql[4][4];
    {
        CP_WAIT(2);
        __syncthreads();
        const uint32_t qbase = smbase + 2 * ASTGB;
        #pragma unroll
        for (int ks = 0; ks < 4; ks++) {
            int rr = w * 16 + (lane & 15);
            int c  = ks * 2 + (lane >> 4);
            uint32_t a = qbase + (uint32_t)rr * 128 + (uint32_t)((c ^ (rr & 7)) << 4);
            LDMX4(qh[ks][0], qh[ks][1], qh[ks][2], qh[ks][3], a);
            LDMX4(ql[ks][0], ql[ks][1], ql[ks][2], ql[ks][3], a + 16384);
        }
    }

    // ---- fragment addressing
    const int fsw = lane & 7;
    uint32_t krow[2];
    #pragma unroll
    for (int jj = 0; jj < 2; jj++)
        krow[jj] = (uint32_t)(jj * 16 + (lane & 7) + ((lane & 16) ? 8 : 0)) * 128;
    const int kc0 = (lane & 8) ? 1 : 0;
    const uint32_t vrow = (uint32_t)((lane & 7) + ((lane & 8) ? 8 : 0)) * 128;
    const int vc0 = (lane & 16) ? 1 : 0;

    float oacc[8][4] = {};
    float lsum0 = 0.f, lsum1 = 0.f;

    int st = 0, stn = 2;
    for (int jt = 0; jt < NT; jt++) {
        if (jt == NT - 1) { CP_WAIT(0); } else { CP_WAIT(1); }
        __syncthreads();
        if (jt + 2 < NT) {
            issue(stn);
            if (++stn == 3) stn = 0;
        }

        const uint32_t base = smbase + st * ASTGB;

        #pragma unroll
        for (int half = 0; half < 2; half++) {
            float sacc[4][4] = {};
            #pragma unroll
            for (int ks = 0; ks < 4; ks++) {
                uint32_t bh[4][2], bl[4][2];
                #pragma unroll
                for (int jj = 0; jj < 2; jj++) {
                    int c = ks * 2 + kc0;
                    uint32_t a = base + krow[jj] + (uint32_t)(half * 32 * 128)
                               + (uint32_t)((c ^ fsw) << 4);
                    LDMX4(bh[2*jj][0], bh[2*jj][1], bh[2*jj+1][0], bh[2*jj+1][1], a);
                    LDMX4(bl[2*jj][0], bl[2*jj][1], bl[2*jj+1][0], bl[2*jj+1][1], a + AMATB);
                }
                #pragma unroll
                for (int n = 0; n < 4; n++) mma_bf16(sacc[n], qh[ks], bh[n]);
                #pragma unroll
                for (int n = 0; n < 4; n++) mma_bf16(sacc[n], qh[ks], bl[n]);
                #pragma unroll
                for (int n = 0; n < 4; n++) mma_bf16(sacc[n], ql[ks], bh[n]);
            }

            uint32_t pah[2][4], pal[2][4];
            #pragma unroll
            for (int n = 0; n < 4; n++) {
                int c0 = jt * 64 + half * 32 + n * 8 + qc;
                bool mk0 = c0 >= cnt, mk1 = (c0 + 1) >= cnt;
                float p00 = mk0 ? 0.f : __expf(sacc[n][0] * 0.125f);
                float p01 = mk1 ? 0.f : __expf(sacc[n][1] * 0.125f);
                float p10 = mk0 ? 0.f : __expf(sacc[n][2] * 0.125f);
                float p11 = mk1 ? 0.f : __expf(sacc[n][3] * 0.125f);
                lsum0 += p00 + p01;
                lsum1 += p10 + p11;
                float h00, l00, h01, l01, h10, l10, h11, l11;
                bsplit(p00, h00, l00); bsplit(p01, h01, l01);
                bsplit(p10, h10, l10); bsplit(p11, h11, l11);
                const int j = n >> 1, o2 = (n & 1) * 2;
                pah[j][o2 + 0] = packbf(h00, h01);
                pah[j][o2 + 1] = packbf(h10, h11);
                pal[j][o2 + 0] = packbf(l00, l01);
                pal[j][o2 + 1] = packbf(l10, l11);
            }

            #pragma unroll
            for (int j = 0; j < 2; j++) {
                #pragma unroll
                for (int g = 0; g < 2; g++) {
                    uint32_t vha[4], vla[4], vhb[4], vlb[4];
                    {
                        int ca = (2 * g) * 2 + vc0;
                        uint32_t aa = base + 2 * AMATB + vrow
                                    + (uint32_t)((half * 32 + j * 16) * 128)
                                    + (uint32_t)((ca ^ fsw) << 4);
                        LDMX4T(vha[0], vha[1], vha[2], vha[3], aa);
                        LDMX4T(vla[0], vla[1], vla[2], vla[3], aa + AMATB);
                        int cb = (2 * g + 1) * 2 + vc0;
                        uint32_t ab = base + 2 * AMATB + vrow
                                    + (uint32_t)((half * 32 + j * 16) * 128)
                                    + (uint32_t)((cb ^ fsw) << 4);
                        LDMX4T(vhb[0], vhb[1], vhb[2], vhb[3], ab);
                        LDMX4T(vlb[0], vlb[1], vlb[2], vlb[3], ab + AMATB);
                    }
                    float* o0 = oacc[4 * g + 0];
                    float* o1 = oacc[4 * g + 1];
                    float* o2 = oacc[4 * g + 2];
                    float* o3 = oacc[4 * g + 3];
                    mma_bf16(o0, pah[j], &vha[0]);
                    mma_bf16(o1, pah[j], &vha[2]);
                    mma_bf16(o2, pah[j], &vhb[0]);
                    mma_bf16(o3, pah[j], &vhb[2]);
                    mma_bf16(o0, pah[j], &vla[0]);
                    mma_bf16(o1, pah[j], &vla[2]);
                    mma_bf16(o2, pah[j], &vlb[0]);
                    mma_bf16(o3, pah[j], &vlb[2]);
                    mma_bf16(o0, pal[j], &vha[0]);
                    mma_bf16(o1, pal[j], &vha[2]);
                    mma_bf16(o2, pal[j], &vhb[0]);
                    mma_bf16(o3, pal[j], &vhb[2]);
                }
            }
        }
        if (++st == 3) st = 0;
    }

    // ---- Normalize, split, store bf16 hi/lo (rows stay permuted)
    lsum0 += __shfl_xor_sync(0xffffffffu, lsum0, 1);
    lsum0 += __shfl_xor_sync(0xffffffffu, lsum0, 2);
    lsum1 += __shfl_xor_sync(0xffffffffu, lsum1, 1);
    lsum1 += __shfl_xor_sync(0xffffffffu, lsum1, 2);
    const float inv0 = 1.0f / lsum0;
    const float inv1 = 1.0f / lsum1;

    #pragma unroll
    for (int d = 0; d < 8; d++) {
        int col = h * DH + d * 8 + qc;
        size_t row = rowb + r0 + qr;
        float h0, l0, h1, l1;
        bsplit(oacc[d][0] * inv0, h0, l0); bsplit(oacc[d][1] * inv0, h1, l1);
        *(uint32_t*)&oh_g[row * CC + col] = packbf(h0, h1);
        *(uint32_t*)&ol_g[row * CC + col] = packbf(l0, l1);
        bsplit(oacc[d][2] * inv1, h0, l0); bsplit(oacc[d][3] * inv1, h1, l1);
        *(uint32_t*)&oh_g[(row + 8) * CC + col] = packbf(h0, h1);
        *(uint32_t*)&ol_g[(row + 8) * CC + col] = packbf(l0, l1);
    }
}

// ---------------------------------------------------------------------------
extern "C" void kernel_launch(void* const* d_in, const int* in_sizes, int n_in,
                              void* d_out, int out_size)
{
    const float* x      = (const float*)d_in[0];
    const int*   mask   = (const int*)  d_in[1];
    const float* w_qkv  = (const float*)d_in[2];
    const float* w_proj = (const float*)d_in[3];
    const float* b_proj = (const float*)d_in[4];
    float* out = (float*)d_out;

    void *pxh, *pxl, *pqh, *pql, *pah, *pal, *pwqh, *pwql, *pwph, *pwpl, *pperm, *pcnt;
    cudaGetSymbolAddress(&pxh, g_xh);   cudaGetSymbolAddress(&pxl, g_xl);
    cudaGetSymbolAddress(&pqh, g_qkvh); cudaGetSymbolAddress(&pql, g_qkvl);
    cudaGetSymbolAddress(&pah, g_atth); cudaGetSymbolAddress(&pal, g_attl);
    cudaGetSymbolAddress(&pwqh, g_wqh); cudaGetSymbolAddress(&pwql, g_wql);
    cudaGetSymbolAddress(&pwph, g_wph); cudaGetSymbolAddress(&pwpl, g_wpl);
    cudaGetSymbolAddress(&pperm, g_perm); cudaGetSymbolAddress(&pcnt, g_cnt);
    __nv_bfloat16 *xh = (__nv_bfloat16*)pxh,  *xl = (__nv_bfloat16*)pxl;
    __nv_bfloat16 *qh = (__nv_bfloat16*)pqh,  *ql = (__nv_bfloat16*)pql;
    __nv_bfloat16 *ah = (__nv_bfloat16*)pah,  *al = (__nv_bfloat16*)pal;
    __nv_bfloat16 *wqh = (__nv_bfloat16*)pwqh, *wql = (__nv_bfloat16*)pwql;
    __nv_bfloat16 *wph = (__nv_bfloat16*)pwph, *wpl = (__nv_bfloat16*)pwpl;
    int *perm = (int*)pperm, *cnt = (int*)pcnt;

    const int GEMM_SMEM = 3 * GSTGB;          // 98304 B -> 2 CTAs/SM
    const int ATTN_SMEM = 3 * ASTGB;          // 98304 B -> 2 CTAs/SM

    // One-time host resources (streams/events are host handles, not device
    // memory; created on the first — non-captured — correctness call, then
    // reused so every call performs identical device work).
    static cudaStream_t sstr[3];
    static cudaEvent_t  evF, evJ[3];
    static bool inited = false;
    if (!inited) {
        for (int i = 0; i < 3; i++)
            cudaStreamCreateWithFlags(&sstr[i], cudaStreamNonBlocking);
        cudaEventCreateWithFlags(&evF, cudaEventDisableTiming);
        for (int i = 0; i < 3; i++)
            cudaEventCreateWithFlags(&evJ[i], cudaEventDisableTiming);
        cudaFuncSetAttribute(gemm_bf16, cudaFuncAttributeMaxDynamicSharedMemorySize, GEMM_SMEM);
        cudaFuncSetAttribute(attn_mma, cudaFuncAttributeMaxDynamicSharedMemorySize, ATTN_SMEM);
        inited = true;
    }

    // ---- Serial prep on the main (default) stream
    compact_kernel<<<BB, NN>>>(mask, perm, cnt);
    splitg_kernel<<<(MROWS * CC / 4 + 255) / 256, 256>>>(x, xh, xl, perm, MROWS * CC / 4);
    {
        dim3 blk(32, 8);
        tsplit2_kernel<<<dim3(CQKV / 32, CC / 32, 2), blk>>>(w_qkv, wqh, wql,
                                                             w_proj, wph, wpl);
    }

    // ---- Fork: 4 concurrent per-batch chains (batch b on stream b%4)
    cudaEventRecord(evF, 0);
    for (int i = 0; i < 3; i++) cudaStreamWaitEvent(sstr[i], evF, 0);

    for (int b = 0; b < BB; b++) {
        cudaStream_t s = (b % 4 == 0) ? (cudaStream_t)0 : sstr[b % 4 - 1];
        // QKV_b (skips K/V tiles of masked rows)
        gemm_bf16<<<dim3(CQKV / 128, NN / 128), 256, GEMM_SMEM, s>>>(
            xh, xl, wqh, wql, nullptr, nullptr, qh, ql, cnt, perm,
            b * NN, CQKV, CC, 1);
        // attn_b over compacted keys
        attn_mma<<<dim3(NN / 128, HH), 256, ATTN_SMEM, s>>>(qh, ql, cnt, ah, al, b);
        // proj_b + bias, rows un-permuted on store
        gemm_bf16<<<dim3(CC / 128, NN / 128), 256, GEMM_SMEM, s>>>(
            ah, al, wph, wpl, b_proj, out, nullptr, nullptr, cnt, perm,
            b * NN, CC, CC, 0);
    }

    // ---- Join side streams back into the main stream
    for (int i = 0; i < 3; i++) {
        cudaEventRecord(evJ[i], sstr[i]);
        cudaStreamWaitEvent((cudaStream_t)0, evJ[i], 0);
    }
}

// round 16
// speedup vs baseline: 1.0737x; 1.0047x over previous
#include <cuda_runtime.h>
#include <cuda_bf16.h>
#include <cstdint>
#include <cstddef>

// Problem constants
#define BB   8
#define NN   1024
#define CC   768
#define HH   12
#define DH   64
#define CQKV 2304            // 3*C
#define MROWS (BB*NN)        // 8192

// Scratch: bf16 hi/lo pairs + permutation (device globals, allocation-free)
__device__ __nv_bfloat16 g_xh[(size_t)MROWS * CC],   g_xl[(size_t)MROWS * CC];
__device__ __nv_bfloat16 g_qkvh[(size_t)MROWS * CQKV], g_qkvl[(size_t)MROWS * CQKV];
__device__ __nv_bfloat16 g_atth[(size_t)MROWS * CC], g_attl[(size_t)MROWS * CC];
__device__ __nv_bfloat16 g_wqh[(size_t)CQKV * CC],   g_wql[(size_t)CQKV * CC];
__device__ __nv_bfloat16 g_wph[(size_t)CC * CC],     g_wpl[(size_t)CC * CC];
__device__ int g_perm[MROWS];    // [b][p] -> original token index (unmasked first)
__device__ int g_cnt[BB];        // unmasked count per batch

// ---------------------------------------------------------------------------
// Helpers
// ---------------------------------------------------------------------------
__device__ __forceinline__ uint32_t smem_u32(const void* p) {
    uint32_t a;
    asm("{ .reg .u64 t; cvta.to.shared.u64 t, %1; cvt.u32.u64 %0, t; }" : "=r"(a) : "l"(p));
    return a;
}
__device__ __forceinline__ void mma_bf16(float* d, const uint32_t* a, const uint32_t* b) {
    asm volatile(
        "mma.sync.aligned.m16n8k16.row.col.f32.bf16.bf16.f32 "
        "{%0,%1,%2,%3}, {%4,%5,%6,%7}, {%8,%9}, {%0,%1,%2,%3};"
        : "+f"(d[0]), "+f"(d[1]), "+f"(d[2]), "+f"(d[3])
        : "r"(a[0]), "r"(a[1]), "r"(a[2]), "r"(a[3]), "r"(b[0]), "r"(b[1]));
}
#define LDMX4(r0, r1, r2, r3, addr) \
    asm volatile("ldmatrix.sync.aligned.m8n8.x4.shared.b16 {%0,%1,%2,%3}, [%4];" \
        : "=r"(r0), "=r"(r1), "=r"(r2), "=r"(r3) : "r"(addr))
#define LDMX4T(r0, r1, r2, r3, addr) \
    asm volatile("ldmatrix.sync.aligned.m8n8.x4.trans.shared.b16 {%0,%1,%2,%3}, [%4];" \
        : "=r"(r0), "=r"(r1), "=r"(r2), "=r"(r3) : "r"(addr))
#define CP_ASYNC16(dst, src) \
    asm volatile("cp.async.cg.shared.global [%0], [%1], 16;" :: "r"(dst), "l"(src) : "memory")
#define CP_COMMIT()   asm volatile("cp.async.commit_group;" ::: "memory")
#define CP_WAIT(n)    asm volatile("cp.async.wait_group %0;" :: "n"(n) : "memory")

__device__ __forceinline__ void bsplit(float x, float& h, float& l) {
    h = __bfloat162float(__float2bfloat16(x));
    l = x - h;
}
__device__ __forceinline__ uint32_t packbf(float e0, float e1) {
    uint32_t d;
    asm("cvt.rn.bf16x2.f32 %0, %1, %2;" : "=r"(d) : "f"(e1), "f"(e0));
    return d;
}

// ---------------------------------------------------------------------------
// Compaction: per-batch stable permutation, unmasked (mask==0) first.
// ---------------------------------------------------------------------------
__global__ void compact_kernel(const int* __restrict__ mask,
                               int* __restrict__ perm, int* __restrict__ cnt)
{
    __shared__ int wc0[32], wo0[32], wc1[32], wo1[32];
    __shared__ int total_s;
    const int b = blockIdx.x, t = threadIdx.x;     // 1024 threads
    const int lane = t & 31, wid = t >> 5;
    const int m = mask[b * NN + t];
    unsigned bal = __ballot_sync(0xffffffffu, m == 0);
    int pre0 = __popc(bal  & ((1u << lane) - 1));
    int pre1 = __popc(~bal & ((1u << lane) - 1));
    if (lane == 0) { wc0[wid] = __popc(bal); wc1[wid] = __popc(~bal); }
    __syncthreads();
    if (t == 0) {
        int s0 = 0, s1 = 0;
        #pragma unroll
        for (int i = 0; i < 32; i++) {
            wo0[i] = s0; s0 += wc0[i];
            wo1[i] = s1; s1 += wc1[i];
        }
        cnt[b] = s0;
        total_s = s0;
    }
    __syncthreads();
    const int total = total_s;
    if (m == 0) perm[b * NN + wo0[wid] + pre0] = t;
    else        perm[b * NN + total + wo1[wid] + pre1] = t;
}

// ---------------------------------------------------------------------------
// Split with row gather (permuted order): dst[p] = split(src[perm[p]])
// ---------------------------------------------------------------------------
__global__ void splitg_kernel(const float* __restrict__ src,
                              __nv_bfloat16* __restrict__ dh,
                              __nv_bfloat16* __restrict__ dl,
                              const int* __restrict__ perm, int n4)
{
    int i = blockIdx.x * blockDim.x + threadIdx.x;
    if (i >= n4) return;
    int row = i / (CC / 4);                        // permuted global row
    int c4  = i - row * (CC / 4);
    int orig = (row & ~(NN - 1)) + perm[row];
    float4 v = *(const float4*)&src[(size_t)orig * CC + c4 * 4];
    float h0, l0, h1, l1, h2, l2, h3, l3;
    bsplit(v.x, h0, l0); bsplit(v.y, h1, l1);
    bsplit(v.z, h2, l2); bsplit(v.w, h3, l3);
    *(uint2*)&dh[i * 4] = make_uint2(packbf(h0, h1), packbf(h2, h3));
    *(uint2*)&dl[i * 4] = make_uint2(packbf(l0, l1), packbf(l2, l3));
}

// ---------------------------------------------------------------------------
// Fused transpose+split for BOTH weight matrices (blockIdx.z selects).
// ---------------------------------------------------------------------------
__global__ void tsplit2_kernel(const float* __restrict__ wq,
                               __nv_bfloat16* __restrict__ wqh, __nv_bfloat16* __restrict__ wql,
                               const float* __restrict__ wp,
                               __nv_bfloat16* __restrict__ wph, __nv_bfloat16* __restrict__ wpl)
{
    const int z = blockIdx.z;
    const int C = z ? CC : CQKV;
    if (z && blockIdx.x >= CC / 32) return;
    const float* src = z ? wp : wq;
    __nv_bfloat16* dh = z ? wph : wqh;
    __nv_bfloat16* dl = z ? wpl : wql;
    const int R = CC;

    __shared__ float tile[32][33];
    int cx = blockIdx.x * 32, ry = blockIdx.y * 32;
    #pragma unroll
    for (int i = 0; i < 32; i += 8)
        tile[threadIdx.y + i][threadIdx.x] = src[(size_t)(ry + threadIdx.y + i) * C + cx + threadIdx.x];
    __syncthreads();
    #pragma unroll
    for (int i = 0; i < 32; i += 8) {
        float v = tile[threadIdx.x][threadIdx.y + i];
        float h, l; bsplit(v, h, l);
        size_t o = (size_t)(cx + threadIdx.y + i) * R + ry + threadIdx.x;
        dh[o] = __float2bfloat16(h);
        dl[o] = __float2bfloat16(l);
    }
}

// ---------------------------------------------------------------------------
// bf16x3 GEMM (BM=128), per-batch row range via mbase. 3-stage pipeline,
// XOR-swizzled dense smem. mode 1 (QKV): skip K/V tiles beyond cntPad.
// mode 0 (proj): fp32 out + bias, rows scattered back via perm.
// ---------------------------------------------------------------------------
#define GMATB  8192                          // bytes: 128 rows x 64B
#define GSTGB  (4 * GMATB)                   // Ah|Al|Bh|Bl = 32768 B

__global__ void __launch_bounds__(256, 2)
gemm_bf16(const __nv_bfloat16* __restrict__ Ah, const __nv_bfloat16* __restrict__ Al,
          const __nv_bfloat16* __restrict__ Bh, const __nv_bfloat16* __restrict__ Bl,
          const float* __restrict__ bias,
          float* __restrict__ Cf,
          __nv_bfloat16* __restrict__ Coh, __nv_bfloat16* __restrict__ Col,
          const int* __restrict__ cnt, const int* __restrict__ perm,
          int mbase, int N, int K, int mode)
{
    const int m0 = mbase + blockIdx.y * 128;
    const int n0 = blockIdx.x * 128;

    // QKV: skip K/V tiles whose rows are all masked tokens
    if (mode == 1 && n0 >= CC) {
        int cp = (cnt[m0 >> 10] + 63) & ~63;
        if ((m0 & (NN - 1)) >= cp) return;
    }

    extern __shared__ __nv_bfloat16 smb[];
    const uint32_t smbase = smem_u32(smb);

    const int tid  = threadIdx.x;
    const int lane = tid & 31;
    const int wid  = tid >> 5;
    const int wm   = wid >> 2;
    const int wn   = wid & 3;
    const int nk   = K / 32;

    // ---- staging: thread owns (rowbase, rowbase+64) x chunk cch in all 4 mats
    const int rb  = tid >> 2;                // 0..63
    const int cch = tid & 3;
    const uint32_t dsoff = (uint32_t)rb * 64 + ((cch ^ ((rb >> 1) & 3)) << 4);
    const __nv_bfloat16* p0 = Ah + (size_t)(m0 + rb) * K + cch * 8;
    const __nv_bfloat16* p1 = Al + (size_t)(m0 + rb) * K + cch * 8;
    const __nv_bfloat16* p2 = Bh + (size_t)(n0 + rb) * K + cch * 8;
    const __nv_bfloat16* p3 = Bl + (size_t)(n0 + rb) * K + cch * 8;
    const size_t rstep = (size_t)64 * K;

    auto issue = [&](int st) {
        uint32_t sb = smbase + st * GSTGB + dsoff;
        CP_ASYNC16(sb,                 p0); CP_ASYNC16(sb + 4096,             p0 + rstep);
        CP_ASYNC16(sb + GMATB,         p1); CP_ASYNC16(sb + GMATB + 4096,     p1 + rstep);
        CP_ASYNC16(sb + 2 * GMATB,     p2); CP_ASYNC16(sb + 2 * GMATB + 4096, p2 + rstep);
        CP_ASYNC16(sb + 3 * GMATB,     p3); CP_ASYNC16(sb + 3 * GMATB + 4096, p3 + rstep);
        CP_COMMIT();
        p0 += 32; p1 += 32; p2 += 32; p3 += 32;
    };

    // ---- fragment addressing (swizzled)
    uint32_t arow[4]; int asw[4];
    #pragma unroll
    for (int mi = 0; mi < 4; mi++) {
        int r = wm * 64 + mi * 16 + (lane & 15);
        arow[mi] = (uint32_t)r * 64;
        asw[mi]  = (r >> 1) & 3;
    }
    const int ac0 = lane >> 4;
    uint32_t brow[2]; int bsw[2];
    #pragma unroll
    for (int nt2 = 0; nt2 < 2; nt2++) {
        int r = wn * 32 + nt2 * 16 + (lane & 7) + ((lane & 16) ? 8 : 0);
        brow[nt2] = (uint32_t)r * 64;
        bsw[nt2]  = (r >> 1) & 3;
    }
    const int bc0 = (lane & 8) ? 1 : 0;

    float acc[4][4][4] = {};

    issue(0);
    issue(1);
    int st = 0, stn = 2;
    for (int kc = 0; kc < nk; kc++) {
        if (kc == nk - 1) { CP_WAIT(0); } else { CP_WAIT(1); }
        __syncthreads();
        if (kc + 2 < nk) {
            issue(stn);
            if (++stn == 3) stn = 0;
        }

        const uint32_t base = smbase + st * GSTGB;
        #pragma unroll
        for (int s = 0; s < 2; s++) {
            uint32_t ah[4][4], al[4][4], bh[4][2], bl[4][2];
            #pragma unroll
            for (int mi = 0; mi < 4; mi++) {
                int c = s * 2 + ac0;
                uint32_t a = base + arow[mi] + (uint32_t)((c ^ asw[mi]) << 4);
                LDMX4(ah[mi][0], ah[mi][1], ah[mi][2], ah[mi][3], a);
                LDMX4(al[mi][0], al[mi][1], al[mi][2], al[mi][3], a + GMATB);
            }
            #pragma unroll
            for (int nt2 = 0; nt2 < 2; nt2++) {
                int c = s * 2 + bc0;
                uint32_t bx = base + 2 * GMATB + brow[nt2] + (uint32_t)((c ^ bsw[nt2]) << 4);
                LDMX4(bh[2*nt2][0], bh[2*nt2][1], bh[2*nt2+1][0], bh[2*nt2+1][1], bx);
                LDMX4(bl[2*nt2][0], bl[2*nt2][1], bl[2*nt2+1][0], bl[2*nt2+1][1], bx + GMATB);
            }
            #pragma unroll
            for (int mi = 0; mi < 4; mi++)
                #pragma unroll
                for (int ni = 0; ni < 4; ni++)
                    mma_bf16(acc[mi][ni], ah[mi], bh[ni]);
            #pragma unroll
            for (int mi = 0; mi < 4; mi++)
                #pragma unroll
                for (int ni = 0; ni < 4; ni++)
                    mma_bf16(acc[mi][ni], ah[mi], bl[ni]);
            #pragma unroll
            for (int mi = 0; mi < 4; mi++)
                #pragma unroll
                for (int ni = 0; ni < 4; ni++)
                    mma_bf16(acc[mi][ni], al[mi], bh[ni]);
        }
        if (++st == 3) st = 0;
    }

    // Epilogue
    #pragma unroll
    for (int mi = 0; mi < 4; mi++) {
        const int row = m0 + wm * 64 + mi * 16 + (lane >> 2);
        #pragma unroll
        for (int ni = 0; ni < 4; ni++) {
            const int col = n0 + wn * 32 + ni * 8 + 2 * (lane & 3);
            float x0 = acc[mi][ni][0], x1 = acc[mi][ni][1];
            float y0 = acc[mi][ni][2], y1 = acc[mi][ni][3];
            if (mode == 0) {
                float b0 = bias ? bias[col] : 0.f, b1 = bias ? bias[col + 1] : 0.f;
                size_t or0 = (size_t)((row & ~(NN - 1)) + perm[row]);
                size_t or1 = (size_t)(((row + 8) & ~(NN - 1)) + perm[row + 8]);
                *(float2*)&Cf[or0 * N + col] = make_float2(x0 + b0, x1 + b1);
                *(float2*)&Cf[or1 * N + col] = make_float2(y0 + b0, y1 + b1);
            } else {
                float h0, l0, h1, l1;
                bsplit(x0, h0, l0); bsplit(x1, h1, l1);
                *(uint32_t*)&Coh[(size_t)row * N + col] = packbf(h0, h1);
                *(uint32_t*)&Col[(size_t)row * N + col] = packbf(l0, l1);
                bsplit(y0, h0, l0); bsplit(y1, h1, l1);
                *(uint32_t*)&Coh[(size_t)(row + 8) * N + col] = packbf(h0, h1);
                *(uint32_t*)&Col[(size_t)(row + 8) * N + col] = packbf(l0, l1);
            }
        }
    }
}

// ---------------------------------------------------------------------------
// Attention bf16x3 flash over COMPACTED keys, per-batch (bsel).
// Q staged into stage-2 smem concurrently with KV stages 0/1.
// ---------------------------------------------------------------------------
#define AMATB  8192                          // bytes: 64 rows x 128B
#define ASTGB  (4 * AMATB)                   // Kh|Kl|Vh|Vl = 32768 B

__global__ void __launch_bounds__(256, 2)
attn_mma(const __nv_bfloat16* __restrict__ qh_g, const __nv_bfloat16* __restrict__ ql_g,
         const int* __restrict__ cntp,
         __nv_bfloat16* __restrict__ oh_g, __nv_bfloat16* __restrict__ ol_g,
         int bsel)
{
    extern __shared__ __nv_bfloat16 sma[];
    const uint32_t smbase = smem_u32(sma);

    const int t    = threadIdx.x;
    const int lane = t & 31;
    const int w    = t >> 5;
    const int q0   = blockIdx.x * 128;
    const int h    = blockIdx.y;
    const int b    = bsel;
    const size_t rowb = (size_t)b * NN;
    const int r0 = q0 + w * 16;
    const int qr = lane >> 2;
    const int qc = (lane & 3) * 2;

    const int cnt = cntp[b];
    int NT = (cnt + 63) >> 6;
    if (NT < 1) NT = 1;

    // ---- K/V staging state
    const int rb  = t >> 3;                  // 0..31
    const int cch = t & 7;
    const uint32_t dsoff = (uint32_t)rb * 128 + ((cch ^ (rb & 7)) << 4);
    const __nv_bfloat16* pH = qh_g + (rowb + rb) * CQKV + CC + h * DH + cch * 8;
    const __nv_bfloat16* pL = ql_g + (rowb + rb) * CQKV + CC + h * DH + cch * 8;
    const size_t rstep = (size_t)32 * CQKV;
    auto issue = [&](int st) {
        uint32_t sb = smbase + st * ASTGB + dsoff;
        CP_ASYNC16(sb,                 pH);      CP_ASYNC16(sb + 4096,             pH + rstep);
        CP_ASYNC16(sb + AMATB,         pL);      CP_ASYNC16(sb + AMATB + 4096,     pL + rstep);
        CP_ASYNC16(sb + 2 * AMATB,     pH + CC); CP_ASYNC16(sb + 2 * AMATB + 4096, pH + CC + rstep);
        CP_ASYNC16(sb + 3 * AMATB,     pL + CC); CP_ASYNC16(sb + 3 * AMATB + 4096, pL + CC + rstep);
        CP_COMMIT();
        pH += (size_t)64 * CQKV;
        pL += (size_t)64 * CQKV;
    };

    // ---- Overlapped prologue: Q tile -> stage-2 smem; KV stage 0/1 in flight
    {
        const __nv_bfloat16* qsH = qh_g + (rowb + q0) * CQKV + h * DH;
        const __nv_bfloat16* qsL = ql_g + (rowb + q0) * CQKV + h * DH;
        const uint32_t qbase = smbase + 2 * ASTGB;
        #pragma unroll
        for (int i = 0; i < 4; i++) {
            int idx = t + i * 256;
            int row = idx >> 3, c = idx & 7;
            uint32_t d = qbase + (uint32_t)row * 128 + (uint32_t)((c ^ (row & 7)) << 4);
            CP_ASYNC16(d,         qsH + (size_t)row * CQKV + c * 8);
            CP_ASYNC16(d + 16384, qsL + (size_t)row * CQKV + c * 8);
        }
        CP_COMMIT();           // group Q
        issue(0);              // group KV0
        issue(1);              // group KV1
    }

    uint32_t qh[4][4], ql[4][4];
    {
        CP_WAIT(2);
        __syncthreads();
        const uint32_t qbase = smbase + 2 * ASTGB;
        #pragma unroll
        for (int ks = 0; ks < 4; ks++) {
            int rr = w * 16 + (lane & 15);
            int c  = ks * 2 + (lane >> 4);
            uint32_t a = qbase + (uint32_t)rr * 128 + (uint32_t)((c ^ (rr & 7)) << 4);
            LDMX4(qh[ks][0], qh[ks][1], qh[ks][2], qh[ks][3], a);
            LDMX4(ql[ks][0], ql[ks][1], ql[ks][2], ql[ks][3], a + 16384);
        }
    }

    // ---- fragment addressing
    const int fsw = lane & 7;
    uint32_t krow[2];
    #pragma unroll
    for (int jj = 0; jj < 2; jj++)
        krow[jj] = (uint32_t)(jj * 16 + (lane & 7) + ((lane & 16) ? 8 : 0)) * 128;
    const int kc0 = (lane & 8) ? 1 : 0;
    const uint32_t vrow = (uint32_t)((lane & 7) + ((lane & 8) ? 8 : 0)) * 128;
    const int vc0 = (lane & 16) ? 1 : 0;

    float oacc[8][4] = {};
    float lsum0 = 0.f, lsum1 = 0.f;

    int st = 0, stn = 2;
    for (int jt = 0; jt < NT; jt++) {
        if (jt == NT - 1) { CP_WAIT(0); } else { CP_WAIT(1); }
        __syncthreads();
        if (jt + 2 < NT) {
            issue(stn);
            if (++stn == 3) stn = 0;
        }

        const uint32_t base = smbase + st * ASTGB;

        #pragma unroll
        for (int half = 0; half < 2; half++) {
            float sacc[4][4] = {};
            #pragma unroll
            for (int ks = 0; ks < 4; ks++) {
                uint32_t bh[4][2], bl[4][2];
                #pragma unroll
                for (int jj = 0; jj < 2; jj++) {
                    int c = ks * 2 + kc0;
                    uint32_t a = base + krow[jj] + (uint32_t)(half * 32 * 128)
                               + (uint32_t)((c ^ fsw) << 4);
                    LDMX4(bh[2*jj][0], bh[2*jj][1], bh[2*jj+1][0], bh[2*jj+1][1], a);
                    LDMX4(bl[2*jj][0], bl[2*jj][1], bl[2*jj+1][0], bl[2*jj+1][1], a + AMATB);
                }
                #pragma unroll
                for (int n = 0; n < 4; n++) mma_bf16(sacc[n], qh[ks], bh[n]);
                #pragma unroll
                for (int n = 0; n < 4; n++) mma_bf16(sacc[n], qh[ks], bl[n]);
                #pragma unroll
                for (int n = 0; n < 4; n++) mma_bf16(sacc[n], ql[ks], bh[n]);
            }

            uint32_t pah[2][4], pal[2][4];
            #pragma unroll
            for (int n = 0; n < 4; n++) {
                int c0 = jt * 64 + half * 32 + n * 8 + qc;
                bool mk0 = c0 >= cnt, mk1 = (c0 + 1) >= cnt;
                float p00 = mk0 ? 0.f : __expf(sacc[n][0] * 0.125f);
                float p01 = mk1 ? 0.f : __expf(sacc[n][1] * 0.125f);
                float p10 = mk0 ? 0.f : __expf(sacc[n][2] * 0.125f);
                float p11 = mk1 ? 0.f : __expf(sacc[n][3] * 0.125f);
                lsum0 += p00 + p01;
                lsum1 += p10 + p11;
                float h00, l00, h01, l01, h10, l10, h11, l11;
                bsplit(p00, h00, l00); bsplit(p01, h01, l01);
                bsplit(p10, h10, l10); bsplit(p11, h11, l11);
                const int j = n >> 1, o2 = (n & 1) * 2;
                pah[j][o2 + 0] = packbf(h00, h01);
                pah[j][o2 + 1] = packbf(h10, h11);
                pal[j][o2 + 0] = packbf(l00, l01);
                pal[j][o2 + 1] = packbf(l10, l11);
            }

            #pragma unroll
            for (int j = 0; j < 2; j++) {
                #pragma unroll
                for (int g = 0; g < 2; g++) {
                    uint32_t vha[4], vla[4], vhb[4], vlb[4];
                    {
                        int ca = (2 * g) * 2 + vc0;
                        uint32_t aa = base + 2 * AMATB + vrow
                                    + (uint32_t)((half * 32 + j * 16) * 128)
                                    + (uint32_t)((ca ^ fsw) << 4);
                        LDMX4T(vha[0], vha[1], vha[2], vha[3], aa);
                        LDMX4T(vla[0], vla[1], vla[2], vla[3], aa + AMATB);
                        int cb = (2 * g + 1) * 2 + vc0;
                        uint32_t ab = base + 2 * AMATB + vrow
                                    + (uint32_t)((half * 32 + j * 16) * 128)
                                    + (uint32_t)((cb ^ fsw) << 4);
                        LDMX4T(vhb[0], vhb[1], vhb[2], vhb[3], ab);
                        LDMX4T(vlb[0], vlb[1], vlb[2], vlb[3], ab + AMATB);
                    }
                    float* o0 = oacc[4 * g + 0];
                    float* o1 = oacc[4 * g + 1];
                    float* o2 = oacc[4 * g + 2];
                    float* o3 = oacc[4 * g + 3];
                    mma_bf16(o0, pah[j], &vha[0]);
                    mma_bf16(o1, pah[j], &vha[2]);
                    mma_bf16(o2, pah[j], &vhb[0]);
                    mma_bf16(o3, pah[j], &vhb[2]);
                    mma_bf16(o0, pah[j], &vla[0]);
                    mma_bf16(o1, pah[j], &vla[2]);
                    mma_bf16(o2, pah[j], &vlb[0]);
                    mma_bf16(o3, pah[j], &vlb[2]);
                    mma_bf16(o0, pal[j], &vha[0]);
                    mma_bf16(o1, pal[j], &vha[2]);
                    mma_bf16(o2, pal[j], &vhb[0]);
                    mma_bf16(o3, pal[j], &vhb[2]);
                }
            }
        }
        if (++st == 3) st = 0;
    }

    // ---- Normalize, split, store bf16 hi/lo (rows stay permuted)
    lsum0 += __shfl_xor_sync(0xffffffffu, lsum0, 1);
    lsum0 += __shfl_xor_sync(0xffffffffu, lsum0, 2);
    lsum1 += __shfl_xor_sync(0xffffffffu, lsum1, 1);
    lsum1 += __shfl_xor_sync(0xffffffffu, lsum1, 2);
    const float inv0 = 1.0f / lsum0;
    const float inv1 = 1.0f / lsum1;

    #pragma unroll
    for (int d = 0; d < 8; d++) {
        int col = h * DH + d * 8 + qc;
        size_t row = rowb + r0 + qr;
        float h0, l0, h1, l1;
        bsplit(oacc[d][0] * inv0, h0, l0); bsplit(oacc[d][1] * inv0, h1, l1);
        *(uint32_t*)&oh_g[row * CC + col] = packbf(h0, h1);
        *(uint32_t*)&ol_g[row * CC + col] = packbf(l0, l1);
        bsplit(oacc[d][2] * inv1, h0, l0); bsplit(oacc[d][3] * inv1, h1, l1);
        *(uint32_t*)&oh_g[(row + 8) * CC + col] = packbf(h0, h1);
        *(uint32_t*)&ol_g[(row + 8) * CC + col] = packbf(l0, l1);
    }
}

// ---------------------------------------------------------------------------
extern "C" void kernel_launch(void* const* d_in, const int* in_sizes, int n_in,
                              void* d_out, int out_size)
{
    const float* x      = (const float*)d_in[0];
    const int*   mask   = (const int*)  d_in[1];
    const float* w_qkv  = (const float*)d_in[2];
    const float* w_proj = (const float*)d_in[3];
    const float* b_proj = (const float*)d_in[4];
    float* out = (float*)d_out;

    void *pxh, *pxl, *pqh, *pql, *pah, *pal, *pwqh, *pwql, *pwph, *pwpl, *pperm, *pcnt;
    cudaGetSymbolAddress(&pxh, g_xh);   cudaGetSymbolAddress(&pxl, g_xl);
    cudaGetSymbolAddress(&pqh, g_qkvh); cudaGetSymbolAddress(&pql, g_qkvl);
    cudaGetSymbolAddress(&pah, g_atth); cudaGetSymbolAddress(&pal, g_attl);
    cudaGetSymbolAddress(&pwqh, g_wqh); cudaGetSymbolAddress(&pwql, g_wql);
    cudaGetSymbolAddress(&pwph, g_wph); cudaGetSymbolAddress(&pwpl, g_wpl);
    cudaGetSymbolAddress(&pperm, g_perm); cudaGetSymbolAddress(&pcnt, g_cnt);
    __nv_bfloat16 *xh = (__nv_bfloat16*)pxh,  *xl = (__nv_bfloat16*)pxl;
    __nv_bfloat16 *qh = (__nv_bfloat16*)pqh,  *ql = (__nv_bfloat16*)pql;
    __nv_bfloat16 *ah = (__nv_bfloat16*)pah,  *al = (__nv_bfloat16*)pal;
    __nv_bfloat16 *wqh = (__nv_bfloat16*)pwqh, *wql = (__nv_bfloat16*)pwql;
    __nv_bfloat16 *wph = (__nv_bfloat16*)pwph, *wpl = (__nv_bfloat16*)pwpl;
    int *perm = (int*)pperm, *cnt = (int*)pcnt;

    const int GEMM_SMEM = 3 * GSTGB;          // 98304 B -> 2 CTAs/SM
    const int ATTN_SMEM = 3 * ASTGB;          // 98304 B -> 2 CTAs/SM

    // One-time host resources — EXACTLY round-14's 3 streams (the validated
    // footprint budget), plus 2 extra small events for the weight-prep fork.
    static cudaStream_t sstr[3];
    static cudaEvent_t  evStart, evF, evW, evJ[3];
    static bool inited = false;
    if (!inited) {
        for (int i = 0; i < 3; i++)
            cudaStreamCreateWithFlags(&sstr[i], cudaStreamNonBlocking);
        cudaEventCreateWithFlags(&evStart, cudaEventDisableTiming);
        cudaEventCreateWithFlags(&evF, cudaEventDisableTiming);
        cudaEventCreateWithFlags(&evW, cudaEventDisableTiming);
        for (int i = 0; i < 3; i++)
            cudaEventCreateWithFlags(&evJ[i], cudaEventDisableTiming);
        cudaFuncSetAttribute(gemm_bf16, cudaFuncAttributeMaxDynamicSharedMemorySize, GEMM_SMEM);
        cudaFuncSetAttribute(attn_mma, cudaFuncAttributeMaxDynamicSharedMemorySize, ATTN_SMEM);
        inited = true;
    }

    // ---- Weight prep on side-stream 2, overlapped with input prep on main
    cudaEventRecord(evStart, 0);
    cudaStreamWaitEvent(sstr[2], evStart, 0);
    {
        dim3 blk(32, 8);
        tsplit2_kernel<<<dim3(CQKV / 32, CC / 32, 2), blk, 0, sstr[2]>>>(
            w_qkv, wqh, wql, w_proj, wph, wpl);
    }
    cudaEventRecord(evW, sstr[2]);

    // ---- Input prep on the main stream
    compact_kernel<<<BB, NN>>>(mask, perm, cnt);
    splitg_kernel<<<(MROWS * CC / 4 + 255) / 256, 256>>>(x, xh, xl, perm, MROWS * CC / 4);
    cudaEventRecord(evF, 0);

    // ---- Fork: 4 concurrent chains (batch b on stream b%4); all wait on
    //      both input-prep (evF) and weight-prep (evW).
    cudaStreamWaitEvent((cudaStream_t)0, evW, 0);
    for (int i = 0; i < 2; i++) {
        cudaStreamWaitEvent(sstr[i], evF, 0);
        cudaStreamWaitEvent(sstr[i], evW, 0);
    }
    cudaStreamWaitEvent(sstr[2], evF, 0);      // stream 2 already ordered after evW

    for (int b = 0; b < BB; b++) {
        cudaStream_t s = (b % 4 == 0) ? (cudaStream_t)0 : sstr[b % 4 - 1];
        // QKV_b (skips K/V tiles of masked rows)
        gemm_bf16<<<dim3(CQKV / 128, NN / 128), 256, GEMM_SMEM, s>>>(
            xh, xl, wqh, wql, nullptr, nullptr, qh, ql, cnt, perm,
            b * NN, CQKV, CC, 1);
        // attn_b over compacted keys
        attn_mma<<<dim3(NN / 128, HH), 256, ATTN_SMEM, s>>>(qh, ql, cnt, ah, al, b);
        // proj_b + bias, rows un-permuted on store
        gemm_bf16<<<dim3(CC / 128, NN / 128), 256, GEMM_SMEM, s>>>(
            ah, al, wph, wpl, b_proj, out, nullptr, nullptr, cnt, perm,
            b * NN, CC, CC, 0);
    }

    // ---- Join side streams back into the main stream
    for (int i = 0; i < 3; i++) {
        cudaEventRecord(evJ[i], sstr[i]);
        cudaStreamWaitEvent((cudaStream_t)0, evJ[i], 0);
    }
}